// round 4
// baseline (speedup 1.0000x reference)
#include <cuda_runtime.h>
#include <cstdint>

#define MAX_N 50000
#define MAX_E 800000
#define D 128
#define SCAN_B 512
#define MAX_BLK 128   // >= ceil(MAX_N/SCAN_B)

// Scratch (device globals: allocation forbidden in kernel_launch)
__device__ int   g_mode;              // 1 = edge_index is int64, 0 = int32
__device__ int   g_deg[MAX_N];        // edge in-degree (excl self-loop)
__device__ int   g_off[MAX_N];        // CSR row offsets
__device__ int   g_cur[MAX_N];        // fill cursors
__device__ int   g_bsum[MAX_BLK];     // scan block sums
__device__ float g_dis[MAX_N];        // rsqrt(deg+1)
__device__ int   g_src[MAX_E];        // CSR column indices (source nodes)

// ---------------------------------------------------------------------------
// dtype probe: reads only the first 32 entries (256 B — within either layout)
__global__ void k_detect(const void* ei, int E, int N) {
    if (threadIdx.x == 0 && blockIdx.x == 0) {
        const long long* p64 = (const long long*)ei;
        int n = E < 32 ? E : 32;
        int ok64 = 1;
        for (int i = 0; i < n; i++) {
            long long v = p64[i];
            if (v < 0 || v >= (long long)N) { ok64 = 0; break; }
        }
        g_mode = ok64;
    }
}

__device__ __forceinline__ int edge_at(const void* ei, long long idx, int mode) {
    if (mode) return (int)((const long long*)ei)[idx];
    return ((const int*)ei)[idx];
}

__global__ void k_zero(int N) {
    int i = blockIdx.x * blockDim.x + threadIdx.x;
    if (i < N) g_deg[i] = 0;
}

__global__ void k_count(const void* __restrict__ ei, int E, int N) {
    int e = blockIdx.x * blockDim.x + threadIdx.x;
    if (e >= E) return;
    int mode = g_mode;
    int d = edge_at(ei, (long long)E + e, mode);
    if (d >= 0 && d < N) atomicAdd(&g_deg[d], 1);
}

// per-block exclusive scan + block sums
__global__ void k_scan_block(int N) {
    __shared__ int sm[SCAN_B];
    int i = blockIdx.x * SCAN_B + threadIdx.x;
    int v = (i < N) ? g_deg[i] : 0;
    sm[threadIdx.x] = v;
    __syncthreads();
#pragma unroll
    for (int o = 1; o < SCAN_B; o <<= 1) {
        int t = (threadIdx.x >= o) ? sm[threadIdx.x - o] : 0;
        __syncthreads();
        sm[threadIdx.x] += t;
        __syncthreads();
    }
    if (i < N) g_off[i] = sm[threadIdx.x] - v;   // exclusive
    if (threadIdx.x == SCAN_B - 1) g_bsum[blockIdx.x] = sm[SCAN_B - 1];
}

__global__ void k_scan_sums(int nb) {
    if (threadIdx.x == 0) {
        int acc = 0;
        for (int b = 0; b < nb; b++) { int t = g_bsum[b]; g_bsum[b] = acc; acc += t; }
    }
}

__global__ void k_finalize(int N) {
    int i = blockIdx.x * blockDim.x + threadIdx.x;
    if (i < N) {
        int o = g_off[i] + g_bsum[i / SCAN_B];
        g_off[i] = o;
        g_cur[i] = o;
        g_dis[i] = rsqrtf((float)(g_deg[i] + 1));
    }
}

__global__ void k_fill(const void* __restrict__ ei, int E, int N) {
    int e = blockIdx.x * blockDim.x + threadIdx.x;
    if (e >= E) return;
    int mode = g_mode;
    int s = edge_at(ei, e, mode);
    int d = edge_at(ei, (long long)E + e, mode);
    if (s >= 0 && s < N && d >= 0 && d < N) {
        int pos = atomicAdd(&g_cur[d], 1);
        if (pos >= 0 && pos < E) g_src[pos] = s;
    }
}

// gather-aggregate: one warp per node, all 4 sets, self-loop included.
// writes y directly into out (d_out used as scratch; GEMM later runs in-place)
__global__ void k_agg(const float* __restrict__ x0, const float* __restrict__ x1,
                      const float* __restrict__ x2, const float* __restrict__ x3,
                      float* __restrict__ out, int N) {
    int gt = blockIdx.x * blockDim.x + threadIdx.x;
    int i = gt >> 5;
    int lane = gt & 31;
    if (i >= N) return;

    float di = g_dis[i];
    float d2 = di * di;
    size_t rv = (size_t)i * 32 + lane;   // float4 index

    const float4* X0 = (const float4*)x0;
    const float4* X1 = (const float4*)x1;
    const float4* X2 = (const float4*)x2;
    const float4* X3 = (const float4*)x3;

    float4 a0 = X0[rv], a1 = X1[rv], a2 = X2[rv], a3 = X3[rv];
    a0.x *= d2; a0.y *= d2; a0.z *= d2; a0.w *= d2;
    a1.x *= d2; a1.y *= d2; a1.z *= d2; a1.w *= d2;
    a2.x *= d2; a2.y *= d2; a2.z *= d2; a2.w *= d2;
    a3.x *= d2; a3.y *= d2; a3.z *= d2; a3.w *= d2;

    int beg = g_off[i];
    int end = beg + g_deg[i];
    for (int j = beg; j < end; j++) {
        int s = g_src[j];
        float w = di * g_dis[s];
        size_t sv = (size_t)s * 32 + lane;
        float4 v0 = X0[sv], v1 = X1[sv], v2 = X2[sv], v3 = X3[sv];
        a0.x = fmaf(v0.x, w, a0.x); a0.y = fmaf(v0.y, w, a0.y);
        a0.z = fmaf(v0.z, w, a0.z); a0.w = fmaf(v0.w, w, a0.w);
        a1.x = fmaf(v1.x, w, a1.x); a1.y = fmaf(v1.y, w, a1.y);
        a1.z = fmaf(v1.z, w, a1.z); a1.w = fmaf(v1.w, w, a1.w);
        a2.x = fmaf(v2.x, w, a2.x); a2.y = fmaf(v2.y, w, a2.y);
        a2.z = fmaf(v2.z, w, a2.z); a2.w = fmaf(v2.w, w, a2.w);
        a3.x = fmaf(v3.x, w, a3.x); a3.y = fmaf(v3.y, w, a3.y);
        a3.z = fmaf(v3.z, w, a3.z); a3.w = fmaf(v3.w, w, a3.w);
    }

    size_t NN = (size_t)N * 32;
    float4* Y = (float4*)out;
    Y[rv]          = a0;
    Y[NN + rv]     = a1;
    Y[2 * NN + rv] = a2;
    Y[3 * NN + rv] = a3;
}

// ---------------------------------------------------------------------------
// In-place GEMM: io_s <- io_s @ W_s^T + b_s.  128x128 tile, 8x8/thread,
// K chunks of 32 fully buffered in smem before any write. Static smem ~34 KB.
#define KC 32
#define PITCH 132
__global__ void k_gemm(const float* __restrict__ W1, const float* __restrict__ b1,
                       const float* __restrict__ W2, const float* __restrict__ b2,
                       float* io, int N) {
    __shared__ __align__(16) float Ws[KC][PITCH];  // Ws[kk][n] = W[n][k0+kk]
    __shared__ __align__(16) float As[KC][PITCH];  // As[kk][m] = y[m0+m][k0+kk]

    int set = blockIdx.y;
    const float* Wp = (set == 0 || set == 2) ? W1 : W2;
    const float* bp = (set == 0 || set == 2) ? b1 : b2;
    float* o = io + (size_t)set * N * D;

    int tid = threadIdx.x;
    int m0 = blockIdx.x * 128;
    int tx = tid & 15, ty = tid >> 4;
    int nb = tx * 8, mb = ty * 8;

    float acc[8][8];
#pragma unroll
    for (int i = 0; i < 8; i++)
#pragma unroll
        for (int j = 0; j < 8; j++) acc[i][j] = 0.0f;

    for (int k0 = 0; k0 < D; k0 += KC) {
        for (int idx = tid; idx < 128 * KC; idx += 256) {
            int n = idx >> 5, kk = idx & 31;
            Ws[kk][n] = Wp[n * D + k0 + kk];
        }
        for (int idx = tid; idx < 128 * KC; idx += 256) {
            int m = idx >> 5, kk = idx & 31;
            int gm = m0 + m;
            As[kk][m] = (gm < N) ? o[(size_t)gm * D + k0 + kk] : 0.0f;
        }
        __syncthreads();

#pragma unroll
        for (int kk = 0; kk < KC; kk++) {
            float4 a0 = *(const float4*)&As[kk][mb];
            float4 a1 = *(const float4*)&As[kk][mb + 4];
            float4 w0 = *(const float4*)&Ws[kk][nb];
            float4 w1 = *(const float4*)&Ws[kk][nb + 4];
            float a[8] = {a0.x, a0.y, a0.z, a0.w, a1.x, a1.y, a1.z, a1.w};
            float w[8] = {w0.x, w0.y, w0.z, w0.w, w1.x, w1.y, w1.z, w1.w};
#pragma unroll
            for (int i = 0; i < 8; i++)
#pragma unroll
                for (int j = 0; j < 8; j++)
                    acc[i][j] = fmaf(a[i], w[j], acc[i][j]);
        }
        __syncthreads();
    }

    float bv[8];
#pragma unroll
    for (int j = 0; j < 8; j++) bv[j] = bp[nb + j];

#pragma unroll
    for (int i = 0; i < 8; i++) {
        int gm = m0 + mb + i;
        if (gm < N) {
            float4 o0 = make_float4(acc[i][0] + bv[0], acc[i][1] + bv[1],
                                    acc[i][2] + bv[2], acc[i][3] + bv[3]);
            float4 o1 = make_float4(acc[i][4] + bv[4], acc[i][5] + bv[5],
                                    acc[i][6] + bv[6], acc[i][7] + bv[7]);
            *(float4*)(o + (size_t)gm * D + nb)     = o0;
            *(float4*)(o + (size_t)gm * D + nb + 4) = o1;
        }
    }
}

// ---------------------------------------------------------------------------
extern "C" void kernel_launch(void* const* d_in, const int* in_sizes, int n_in,
                              void* d_out, int out_size) {
    const float* x0 = (const float*)d_in[0];  // x_r1 (W1)
    const float* x1 = (const float*)d_in[1];  // x_r2 (W2)
    const float* x2 = (const float*)d_in[2];  // x_i1 (W1)
    const float* x3 = (const float*)d_in[3];  // x_i2 (W2)
    const void*  ei = d_in[4];                // edge_index: int64 OR int32
    const float* W1 = (const float*)d_in[5];
    const float* b1 = (const float*)d_in[6];
    const float* W2 = (const float*)d_in[7];
    const float* b2 = (const float*)d_in[8];
    float* out = (float*)d_out;

    int N = in_sizes[0] / D;
    int E = in_sizes[4] / 2;
    int nb_scan = (N + SCAN_B - 1) / SCAN_B;

    // dtype probe + CSR build + normalization
    k_detect<<<1, 32>>>(ei, E, N);
    k_zero<<<(N + 255) / 256, 256>>>(N);
    k_count<<<(E + 255) / 256, 256>>>(ei, E, N);
    k_scan_block<<<nb_scan, SCAN_B>>>(N);
    k_scan_sums<<<1, 32>>>(nb_scan);
    k_finalize<<<(N + 255) / 256, 256>>>(N);
    k_fill<<<(E + 255) / 256, 256>>>(ei, E, N);

    // gather-aggregate into d_out (scratch)
    {
        long long threads = (long long)N * 32;
        int blocks = (int)((threads + 255) / 256);
        k_agg<<<blocks, 256>>>(x0, x1, x2, x3, out, N);
    }

    // in-place GEMM + bias
    {
        dim3 grid((N + 127) / 128, 4);
        k_gemm<<<grid, 256>>>(W1, b1, W2, b2, out, N);
    }
}

// round 5
// speedup vs baseline: 1.3721x; 1.3721x over previous
#include <cuda_runtime.h>
#include <cstdint>

#define MAX_N 50000
#define MAX_E 800000
#define D 128
#define SCAN_B 512
#define MAX_BLK 128   // >= ceil(MAX_N/SCAN_B)

// Scratch (device globals: allocation forbidden in kernel_launch)
__device__ int   g_mode;              // 1 = edge_index is int64, 0 = int32
__device__ int   g_deg[MAX_N];        // edge in-degree (excl self-loop)
__device__ int   g_off[MAX_N];        // CSR row offsets
__device__ int   g_cur[MAX_N];        // fill cursors
__device__ int   g_bsum[MAX_BLK];     // scan block sums
__device__ float g_dis[MAX_N];        // rsqrt(deg+1)
__device__ int   g_src[MAX_E];        // CSR column indices (source nodes)

// ---------------------------------------------------------------------------
// dtype probe: reads only the first 32 entries (256 B — within either layout)
__global__ void k_detect(const void* ei, int E, int N) {
    if (threadIdx.x == 0 && blockIdx.x == 0) {
        const long long* p64 = (const long long*)ei;
        int n = E < 32 ? E : 32;
        int ok64 = 1;
        for (int i = 0; i < n; i++) {
            long long v = p64[i];
            if (v < 0 || v >= (long long)N) { ok64 = 0; break; }
        }
        g_mode = ok64;
    }
}

__device__ __forceinline__ int edge_at(const void* ei, long long idx, int mode) {
    if (mode) return (int)((const long long*)ei)[idx];
    return ((const int*)ei)[idx];
}

__global__ void k_zero(int N) {
    int i = blockIdx.x * blockDim.x + threadIdx.x;
    if (i < N) g_deg[i] = 0;
}

__global__ void k_count(const void* __restrict__ ei, int E, int N) {
    int e = blockIdx.x * blockDim.x + threadIdx.x;
    if (e >= E) return;
    int mode = g_mode;
    int d = edge_at(ei, (long long)E + e, mode);
    if (d >= 0 && d < N) atomicAdd(&g_deg[d], 1);
}

__global__ void k_scan_block(int N) {
    __shared__ int sm[SCAN_B];
    int i = blockIdx.x * SCAN_B + threadIdx.x;
    int v = (i < N) ? g_deg[i] : 0;
    sm[threadIdx.x] = v;
    __syncthreads();
#pragma unroll
    for (int o = 1; o < SCAN_B; o <<= 1) {
        int t = (threadIdx.x >= o) ? sm[threadIdx.x - o] : 0;
        __syncthreads();
        sm[threadIdx.x] += t;
        __syncthreads();
    }
    if (i < N) g_off[i] = sm[threadIdx.x] - v;   // exclusive
    if (threadIdx.x == SCAN_B - 1) g_bsum[blockIdx.x] = sm[SCAN_B - 1];
}

__global__ void k_scan_sums(int nb) {
    if (threadIdx.x == 0) {
        int acc = 0;
        for (int b = 0; b < nb; b++) { int t = g_bsum[b]; g_bsum[b] = acc; acc += t; }
    }
}

__global__ void k_finalize(int N) {
    int i = blockIdx.x * blockDim.x + threadIdx.x;
    if (i < N) {
        int o = g_off[i] + g_bsum[i / SCAN_B];
        g_off[i] = o;
        g_cur[i] = o;
        g_dis[i] = rsqrtf((float)(g_deg[i] + 1));
    }
}

__global__ void k_fill(const void* __restrict__ ei, int E, int N) {
    int e = blockIdx.x * blockDim.x + threadIdx.x;
    if (e >= E) return;
    int mode = g_mode;
    int s = edge_at(ei, e, mode);
    int d = edge_at(ei, (long long)E + e, mode);
    if (s >= 0 && s < N && d >= 0 && d < N) {
        int pos = atomicAdd(&g_cur[d], 1);
        if (pos >= 0 && pos < E) g_src[pos] = s;
    }
}

// gather-aggregate: one warp per node, all 4 sets, self-loop included.
// writes y directly into out (d_out used as scratch; GEMM later runs in-place)
__global__ void k_agg(const float* __restrict__ x0, const float* __restrict__ x1,
                      const float* __restrict__ x2, const float* __restrict__ x3,
                      float* __restrict__ out, int N) {
    int gt = blockIdx.x * blockDim.x + threadIdx.x;
    int i = gt >> 5;
    int lane = gt & 31;
    if (i >= N) return;

    float di = g_dis[i];
    float d2 = di * di;
    size_t rv = (size_t)i * 32 + lane;   // float4 index

    const float4* X0 = (const float4*)x0;
    const float4* X1 = (const float4*)x1;
    const float4* X2 = (const float4*)x2;
    const float4* X3 = (const float4*)x3;

    float4 a0 = X0[rv], a1 = X1[rv], a2 = X2[rv], a3 = X3[rv];
    a0.x *= d2; a0.y *= d2; a0.z *= d2; a0.w *= d2;
    a1.x *= d2; a1.y *= d2; a1.z *= d2; a1.w *= d2;
    a2.x *= d2; a2.y *= d2; a2.z *= d2; a2.w *= d2;
    a3.x *= d2; a3.y *= d2; a3.z *= d2; a3.w *= d2;

    int beg = g_off[i];
    int end = beg + g_deg[i];
    for (int j = beg; j < end; j++) {
        int s = g_src[j];
        float w = di * g_dis[s];
        size_t sv = (size_t)s * 32 + lane;
        float4 v0 = X0[sv], v1 = X1[sv], v2 = X2[sv], v3 = X3[sv];
        a0.x = fmaf(v0.x, w, a0.x); a0.y = fmaf(v0.y, w, a0.y);
        a0.z = fmaf(v0.z, w, a0.z); a0.w = fmaf(v0.w, w, a0.w);
        a1.x = fmaf(v1.x, w, a1.x); a1.y = fmaf(v1.y, w, a1.y);
        a1.z = fmaf(v1.z, w, a1.z); a1.w = fmaf(v1.w, w, a1.w);
        a2.x = fmaf(v2.x, w, a2.x); a2.y = fmaf(v2.y, w, a2.y);
        a2.z = fmaf(v2.z, w, a2.z); a2.w = fmaf(v2.w, w, a2.w);
        a3.x = fmaf(v3.x, w, a3.x); a3.y = fmaf(v3.y, w, a3.y);
        a3.z = fmaf(v3.z, w, a3.z); a3.w = fmaf(v3.w, w, a3.w);
    }

    size_t NN = (size_t)N * 32;
    float4* Y = (float4*)out;
    Y[rv]          = a0;
    Y[NN + rv]     = a1;
    Y[2 * NN + rv] = a2;
    Y[3 * NN + rv] = a3;
}

// ---------------------------------------------------------------------------
// In-place GEMM on tensor cores: io_s <- io_s @ W_s^T + b_s  (tf32 mma, f32 acc)
// Block 128(M)x128(N), 8 warps as 2(M)x4(N) -> warp tile 64x32.
// K chunked by 32; operands tf32-converted at smem-store time.
#define KC 32
#define APITCH 36   // (4g+c)%32 -> conflict-free fragment loads

__device__ __forceinline__ uint32_t f2tf32(float f) {
    uint32_t u;
    asm("cvt.rna.tf32.f32 %0, %1;" : "=r"(u) : "f"(f));
    return u;
}

__device__ __forceinline__ void mma_tf32(float* d, const uint32_t* a, const uint32_t* b) {
    asm volatile(
        "mma.sync.aligned.m16n8k8.row.col.f32.tf32.tf32.f32 "
        "{%0,%1,%2,%3}, {%4,%5,%6,%7}, {%8,%9}, {%0,%1,%2,%3};"
        : "+f"(d[0]), "+f"(d[1]), "+f"(d[2]), "+f"(d[3])
        : "r"(a[0]), "r"(a[1]), "r"(a[2]), "r"(a[3]), "r"(b[0]), "r"(b[1]));
}

__global__ void __launch_bounds__(256) k_gemm(
        const float* __restrict__ W1, const float* __restrict__ b1,
        const float* __restrict__ W2, const float* __restrict__ b2,
        float* io, int N) {
    __shared__ uint32_t As[128][APITCH];  // y tile  [m][k], tf32 bits
    __shared__ uint32_t Ws[128][APITCH];  // W tile  [n][k], tf32 bits (B col-major)

    int set = blockIdx.y;
    const float* Wp = (set == 0 || set == 2) ? W1 : W2;
    const float* bp = (set == 0 || set == 2) ? b1 : b2;
    float* o = io + (size_t)set * N * D;

    int tid = threadIdx.x;
    int m0 = blockIdx.x * 128;
    int warp = tid >> 5, lane = tid & 31;
    int wm = warp >> 2, wn = warp & 3;        // 2 x 4 warp grid
    int g = lane >> 2, c = lane & 3;

    float acc[4][4][4];
#pragma unroll
    for (int mi = 0; mi < 4; mi++)
#pragma unroll
        for (int ni = 0; ni < 4; ni++)
#pragma unroll
            for (int r = 0; r < 4; r++) acc[mi][ni][r] = 0.0f;

    for (int k0 = 0; k0 < D; k0 += KC) {
        // stage y tile (guarded) and W tile, converting to tf32
        for (int idx = tid; idx < 128 * (KC / 4); idx += 256) {
            int m = idx >> 3, k4 = (idx & 7) << 2;
            int gm = m0 + m;
            float4 v = make_float4(0.f, 0.f, 0.f, 0.f);
            if (gm < N) v = *(const float4*)&o[(size_t)gm * D + k0 + k4];
            As[m][k4 + 0] = f2tf32(v.x);
            As[m][k4 + 1] = f2tf32(v.y);
            As[m][k4 + 2] = f2tf32(v.z);
            As[m][k4 + 3] = f2tf32(v.w);
        }
        for (int idx = tid; idx < 128 * (KC / 4); idx += 256) {
            int n = idx >> 3, k4 = (idx & 7) << 2;
            float4 v = *(const float4*)&Wp[n * D + k0 + k4];
            Ws[n][k4 + 0] = f2tf32(v.x);
            Ws[n][k4 + 1] = f2tf32(v.y);
            Ws[n][k4 + 2] = f2tf32(v.z);
            Ws[n][k4 + 3] = f2tf32(v.w);
        }
        __syncthreads();

#pragma unroll
        for (int ks = 0; ks < KC / 8; ks++) {
            int kk = ks * 8;
            uint32_t a[4][4], b[4][2];
#pragma unroll
            for (int mi = 0; mi < 4; mi++) {
                int r = wm * 64 + mi * 16 + g;
                a[mi][0] = As[r][kk + c];
                a[mi][1] = As[r + 8][kk + c];
                a[mi][2] = As[r][kk + c + 4];
                a[mi][3] = As[r + 8][kk + c + 4];
            }
#pragma unroll
            for (int ni = 0; ni < 4; ni++) {
                int n = wn * 32 + ni * 8 + g;
                b[ni][0] = Ws[n][kk + c];
                b[ni][1] = Ws[n][kk + c + 4];
            }
#pragma unroll
            for (int mi = 0; mi < 4; mi++)
#pragma unroll
                for (int ni = 0; ni < 4; ni++)
                    mma_tf32(acc[mi][ni], a[mi], b[ni]);
        }
        __syncthreads();
    }

    // epilogue: add bias, write f32x2 per fragment row
#pragma unroll
    for (int ni = 0; ni < 4; ni++) {
        int cb = wn * 32 + ni * 8 + 2 * c;
        float bv0 = bp[cb], bv1 = bp[cb + 1];
#pragma unroll
        for (int mi = 0; mi < 4; mi++) {
            int r0 = m0 + wm * 64 + mi * 16 + g;
            int r1 = r0 + 8;
            if (r0 < N) {
                float2 v = make_float2(acc[mi][ni][0] + bv0, acc[mi][ni][1] + bv1);
                *(float2*)&o[(size_t)r0 * D + cb] = v;
            }
            if (r1 < N) {
                float2 v = make_float2(acc[mi][ni][2] + bv0, acc[mi][ni][3] + bv1);
                *(float2*)&o[(size_t)r1 * D + cb] = v;
            }
        }
    }
}

// ---------------------------------------------------------------------------
extern "C" void kernel_launch(void* const* d_in, const int* in_sizes, int n_in,
                              void* d_out, int out_size) {
    const float* x0 = (const float*)d_in[0];  // x_r1 (W1)
    const float* x1 = (const float*)d_in[1];  // x_r2 (W2)
    const float* x2 = (const float*)d_in[2];  // x_i1 (W1)
    const float* x3 = (const float*)d_in[3];  // x_i2 (W2)
    const void*  ei = d_in[4];                // edge_index: int64 OR int32
    const float* W1 = (const float*)d_in[5];
    const float* b1 = (const float*)d_in[6];
    const float* W2 = (const float*)d_in[7];
    const float* b2 = (const float*)d_in[8];
    float* out = (float*)d_out;

    int N = in_sizes[0] / D;
    int E = in_sizes[4] / 2;
    int nb_scan = (N + SCAN_B - 1) / SCAN_B;

    // dtype probe + CSR build + normalization
    k_detect<<<1, 32>>>(ei, E, N);
    k_zero<<<(N + 255) / 256, 256>>>(N);
    k_count<<<(E + 255) / 256, 256>>>(ei, E, N);
    k_scan_block<<<nb_scan, SCAN_B>>>(N);
    k_scan_sums<<<1, 32>>>(nb_scan);
    k_finalize<<<(N + 255) / 256, 256>>>(N);
    k_fill<<<(E + 255) / 256, 256>>>(ei, E, N);

    // gather-aggregate into d_out (scratch)
    {
        long long threads = (long long)N * 32;
        int blocks = (int)((threads + 255) / 256);
        k_agg<<<blocks, 256>>>(x0, x1, x2, x3, out, N);
    }

    // in-place tensor-core GEMM + bias
    {
        dim3 grid((N + 127) / 128, 4);
        k_gemm<<<grid, 256>>>(W1, b1, W2, b2, out, N);
    }
}